// round 7
// baseline (speedup 1.0000x reference)
#include <cuda_runtime.h>
#include <math.h>
#include <stdint.h>

#define HID 1024
#define NHEAD 16
#define DHEAD 64
#define RVOC 32
#define SEQ 2048

// ---------------------------------------------------------------------------
// Scratch (no allocations allowed -> __device__ globals)
// ---------------------------------------------------------------------------
__device__ float g_Q[SEQ * HID];    // tf32-rounded by gemm epilogue
__device__ float g_K[SEQ * HID];    // tf32-rounded
__device__ float g_V[SEQ * HID];    // tf32-rounded
__device__ float g_ctx[SEQ * HID];  // fp32

// ---------------------------------------------------------------------------
// helpers
// ---------------------------------------------------------------------------
__device__ __forceinline__ float tf32r(float x) {
    asm("cvt.rna.tf32.f32 %0, %0;" : "+f"(x));
    return x;
}
__device__ __forceinline__ float4 tf32r4(float4 v) {
    v.x = tf32r(v.x); v.y = tf32r(v.y); v.z = tf32r(v.z); v.w = tf32r(v.w);
    return v;
}
__device__ __forceinline__ void mma_tf32(float* c, const float* a, const float* b) {
    const uint32_t* A = reinterpret_cast<const uint32_t*>(a);
    const uint32_t* B = reinterpret_cast<const uint32_t*>(b);
    asm volatile(
        "mma.sync.aligned.m16n8k8.row.col.f32.tf32.tf32.f32 "
        "{%0,%1,%2,%3}, {%4,%5,%6,%7}, {%8,%9}, {%0,%1,%2,%3};\n"
        : "+f"(c[0]), "+f"(c[1]), "+f"(c[2]), "+f"(c[3])
        : "r"(A[0]), "r"(A[1]), "r"(A[2]), "r"(A[3]), "r"(B[0]), "r"(B[1]));
}
__device__ __forceinline__ uint32_t s2u(const void* p) {
    return (uint32_t)__cvta_generic_to_shared(p);
}
#define CPA16(dst, src) \
    asm volatile("cp.async.ca.shared.global [%0], [%1], 16;\n" :: "r"(dst), "l"(src))
#define CPCOMMIT() asm volatile("cp.async.commit_group;\n")
#define CPWAIT(n)  asm volatile("cp.async.wait_group %0;\n" :: "n"(n))

// ---------------------------------------------------------------------------
// tf32 tensor-core GEMM: C[M,N] = A[M,K] @ B[K,N] + bias[N]
// 128x64 block tile, BK=16, 256 threads = 8 warps (4m x 2n), warp tile 32x32.
// Grid is N/64 x M/128 = 16x16 = 256 blocks -> all co-resident at 2 blocks/SM.
// ROUND=1: write tf32-rounded output (feeds attention fragments directly).
// ---------------------------------------------------------------------------
#define SA 20
#define SB 72

template<int ROUND>
__global__ __launch_bounds__(256, 2) void gemm_tf32(
    const float* __restrict__ A, const float* __restrict__ B,
    const float* __restrict__ bias, float* __restrict__ C,
    int M, int N, int K)
{
    __shared__ float As[128 * SA];
    __shared__ float Bs[16 * SB];

    const int tid  = threadIdx.x;
    const int lane = tid & 31;
    const int wid  = tid >> 5;
    const int g    = lane >> 2;
    const int t    = lane & 3;
    const int wm   = (wid & 3) * 32;
    const int wn   = (wid >> 2) * 32;
    const int brow = blockIdx.y * 128;
    const int bcol = blockIdx.x * 64;

    const int arow = tid >> 1;          // 0..127
    const int akc  = (tid & 1) * 8;     // 0 or 8
    const int br   = tid >> 4;          // 0..15
    const int bnc  = (tid & 15) * 4;    // 0..60

    float acc[2][4][4];
    #pragma unroll
    for (int mt = 0; mt < 2; mt++)
        #pragma unroll
        for (int nt = 0; nt < 4; nt++)
            #pragma unroll
            for (int i = 0; i < 4; i++) acc[mt][nt][i] = 0.f;

    float4 pa0 = *(const float4*)&A[(size_t)(brow + arow) * K + akc];
    float4 pa1 = *(const float4*)&A[(size_t)(brow + arow) * K + akc + 4];
    float4 pb0 = *(const float4*)&B[(size_t)br * N + bcol + bnc];

    for (int k0 = 0; k0 < K; k0 += 16) {
        *(float4*)&As[arow * SA + akc]     = tf32r4(pa0);
        *(float4*)&As[arow * SA + akc + 4] = tf32r4(pa1);
        *(float4*)&Bs[br * SB + bnc]       = tf32r4(pb0);
        __syncthreads();

        int k1 = k0 + 16;
        if (k1 < K) {
            pa0 = *(const float4*)&A[(size_t)(brow + arow) * K + k1 + akc];
            pa1 = *(const float4*)&A[(size_t)(brow + arow) * K + k1 + akc + 4];
            pb0 = *(const float4*)&B[(size_t)(k1 + br) * N + bcol + bnc];
        }

        #pragma unroll
        for (int ks = 0; ks < 16; ks += 8) {
            float a[2][4], b[4][2];
            #pragma unroll
            for (int mt = 0; mt < 2; mt++) {
                a[mt][0] = As[(wm + mt * 16 + g)     * SA + ks + t];
                a[mt][1] = As[(wm + mt * 16 + g + 8) * SA + ks + t];
                a[mt][2] = As[(wm + mt * 16 + g)     * SA + ks + t + 4];
                a[mt][3] = As[(wm + mt * 16 + g + 8) * SA + ks + t + 4];
            }
            #pragma unroll
            for (int nt = 0; nt < 4; nt++) {
                b[nt][0] = Bs[(ks + t)     * SB + wn + nt * 8 + g];
                b[nt][1] = Bs[(ks + t + 4) * SB + wn + nt * 8 + g];
            }
            #pragma unroll
            for (int mt = 0; mt < 2; mt++)
                #pragma unroll
                for (int nt = 0; nt < 4; nt++)
                    mma_tf32(acc[mt][nt], a[mt], b[nt]);
        }
        __syncthreads();
    }

    #pragma unroll
    for (int nt = 0; nt < 4; nt++) {
        const int col = bcol + wn + nt * 8 + 2 * t;
        float2 bv = *(const float2*)&bias[col];
        #pragma unroll
        for (int mt = 0; mt < 2; mt++) {
            int r0 = brow + wm + mt * 16 + g;
            float2 c01 = make_float2(acc[mt][nt][0] + bv.x, acc[mt][nt][1] + bv.y);
            float2 c23 = make_float2(acc[mt][nt][2] + bv.x, acc[mt][nt][3] + bv.y);
            if (ROUND) {
                c01.x = tf32r(c01.x); c01.y = tf32r(c01.y);
                c23.x = tf32r(c23.x); c23.y = tf32r(c23.y);
            }
            *(float2*)&C[(size_t)r0 * N + col]       = c01;
            *(float2*)&C[(size_t)(r0 + 8) * N + col] = c23;
        }
    }
}

// ---------------------------------------------------------------------------
// Flash attention, tf32 mma, cp.async K/V pipeline.
// Block = (64 q rows, 1 head), 128 thr, 4 warps; warp = 16q x 64keys.
// smem (floats), 64KB total -> 3 blocks/SM:
//   QPs[64][76]  Q tile (prologue) then P tile (mainloop)     0     .. 4864
//   Ks [64][68]  K tile (cp.async)                            4864  .. 9216
//   Vs [64][72]  V tile (cp.async)                            9216  .. 13824
//   Es [64][40]  rel_emb^T (prologue) / Rs[64][32] (mainloop) 13824 .. 16384
// ---------------------------------------------------------------------------
#define SQP 76
#define SKK 68
#define SVV 72
#define SEE 40
#define OFF_K  4864
#define OFF_V  9216
#define OFF_RE 13824
#define ATTN_SMEM_FLOATS 16384
#define ATTN_SMEM_BYTES  (ATTN_SMEM_FLOATS * 4)

__global__ __launch_bounds__(128, 3) void attn_kernel(
    const int* __restrict__ att_mask, const int* __restrict__ rel_ids,
    const float* __restrict__ rel_emb, const float* __restrict__ rel_bias)
{
    extern __shared__ float sm[];
    float* QPs = sm;
    float* Ks  = sm + OFF_K;
    float* Vs  = sm + OFF_V;
    float* Es  = sm + OFF_RE;
    float* Rs  = sm + OFF_RE;   // overlays Es after prologue

    const int h    = blockIdx.y;
    const int q0   = blockIdx.x * 64;
    const int tid  = threadIdx.x;
    const int lane = tid & 31;
    const int wid  = tid >> 5;
    const int g    = lane >> 2;
    const int t    = lane & 3;
    const int wq   = wid * 16;

    const uint32_t ksu = s2u(Ks);
    const uint32_t vsu = s2u(Vs);

    // ---- issue cp.async for K(0), V(0) first (overlap with prologue) ----
    #pragma unroll
    for (int j = 0; j < 8; j++) {
        int idx = tid + 128 * j;
        int row = idx >> 4, c4 = (idx & 15) * 4;
        CPA16(ksu + (row * SKK + c4) * 4,
              &g_K[(size_t)row * HID + h * DHEAD + c4]);
    }
    CPCOMMIT();
    #pragma unroll
    for (int j = 0; j < 8; j++) {
        int idx = tid + 128 * j;
        int row = idx >> 4, c4 = (idx & 15) * 4;
        CPA16(vsu + (row * SVV + c4) * 4,
              &g_V[(size_t)row * HID + h * DHEAD + c4]);
    }
    CPCOMMIT();

    // ---- stage Q (already tf32) and rel_emb^T (cvt here) ----
    #pragma unroll
    for (int i = tid; i < 64 * 16; i += 128) {
        int row = i >> 4, dc = (i & 15) * 4;
        *(float4*)&QPs[row * SQP + dc] =
            *(const float4*)&g_Q[(size_t)(q0 + row) * HID + h * DHEAD + dc];
    }
    #pragma unroll
    for (int i = tid; i < 32 * 16; i += 128) {
        int r = i >> 4, dc = (i & 15) * 4;
        float4 v = *(const float4*)&rel_emb[((size_t)r * NHEAD + h) * DHEAD + dc];
        Es[(dc + 0) * SEE + r] = tf32r(v.x);
        Es[(dc + 1) * SEE + r] = tf32r(v.y);
        Es[(dc + 2) * SEE + r] = tf32r(v.z);
        Es[(dc + 3) * SEE + r] = tf32r(v.w);
    }
    __syncthreads();

    // ---- hoist Q A-fragments ----
    float qa[8][4];
    #pragma unroll
    for (int ks = 0; ks < 8; ks++) {
        qa[ks][0] = QPs[(wq + g)     * SQP + ks * 8 + t];
        qa[ks][1] = QPs[(wq + g + 8) * SQP + ks * 8 + t];
        qa[ks][2] = QPs[(wq + g)     * SQP + ks * 8 + t + 4];
        qa[ks][3] = QPs[(wq + g + 8) * SQP + ks * 8 + t + 4];
    }

    // ---- rel scores: rc = Qtile @ E (then Rs = rc + bias) ----
    float rc[4][4];
    #pragma unroll
    for (int nt = 0; nt < 4; nt++)
        #pragma unroll
        for (int i = 0; i < 4; i++) rc[nt][i] = 0.f;
    #pragma unroll
    for (int ks = 0; ks < 8; ks++)
        #pragma unroll
        for (int nt = 0; nt < 4; nt++) {
            float b[2];
            b[0] = Es[(ks * 8 + t)     * SEE + nt * 8 + g];
            b[1] = Es[(ks * 8 + t + 4) * SEE + nt * 8 + g];
            mma_tf32(rc[nt], qa[ks], b);
        }
    __syncthreads();   // everyone done reading Es before Rs overwrites it
    #pragma unroll
    for (int nt = 0; nt < 4; nt++) {
        int r = nt * 8 + 2 * t;
        float bx = rel_bias[(size_t)r * NHEAD + h];
        float by = rel_bias[(size_t)(r + 1) * NHEAD + h];
        Rs[(wq + g)     * 32 + r]     = rc[nt][0] + bx;
        Rs[(wq + g)     * 32 + r + 1] = rc[nt][1] + by;
        Rs[(wq + g + 8) * 32 + r]     = rc[nt][2] + bx;
        Rs[(wq + g + 8) * 32 + r + 1] = rc[nt][3] + by;
    }
    __syncwarp();      // gathers only read this warp's own rows

    float oacc[8][4];
    #pragma unroll
    for (int nt = 0; nt < 8; nt++)
        #pragma unroll
        for (int i = 0; i < 4; i++) oacc[nt][i] = 0.f;
    float m0 = -1e30f, m1 = -1e30f, l0 = 0.f, l1 = 0.f;

    const int qr0 = q0 + wq + g;
    const int qr1 = qr0 + 8;
    const float* rrow0 = &Rs[(wq + g) * 32];
    const float* rrow1 = &Rs[(wq + g + 8) * 32];

    for (int tile = 0; tile < SEQ / 64; tile++) {
        const int k0 = tile * 64;

        CPWAIT(1);          // K(tile) arrived (V may still be in flight)
        __syncthreads();

        // ---- S = Q @ K^T ----
        float s[8][4];
        #pragma unroll
        for (int nt = 0; nt < 8; nt++)
            #pragma unroll
            for (int i = 0; i < 4; i++) s[nt][i] = 0.f;
        #pragma unroll
        for (int ks = 0; ks < 8; ks++)
            #pragma unroll
            for (int nt = 0; nt < 8; nt++) {
                float b[2];
                b[0] = Ks[(nt * 8 + g) * SKK + ks * 8 + t];
                b[1] = Ks[(nt * 8 + g) * SKK + ks * 8 + t + 4];
                mma_tf32(s[nt], qa[ks], b);
            }

        CPWAIT(0);          // V(tile) arrived
        __syncthreads();    // everyone done reading Ks -> safe to refill

        if (tile + 1 < SEQ / 64) {      // prefetch K(tile+1), overlaps below
            #pragma unroll
            for (int j = 0; j < 8; j++) {
                int idx = tid + 128 * j;
                int row = idx >> 4, c4 = (idx & 15) * 4;
                CPA16(ksu + (row * SKK + c4) * 4,
                      &g_K[(size_t)(k0 + 64 + row) * HID + h * DHEAD + c4]);
            }
            CPCOMMIT();
        }

        // ---- + rel gather, scale, mask ----
        #pragma unroll
        for (int nt = 0; nt < 8; nt++) {
            const int col = k0 + nt * 8 + 2 * t;
            int2 id0 = *(const int2*)&rel_ids[(size_t)qr0 * SEQ + col];
            int2 id1 = *(const int2*)&rel_ids[(size_t)qr1 * SEQ + col];
            int2 mk0 = *(const int2*)&att_mask[(size_t)qr0 * SEQ + col];
            int2 mk1 = *(const int2*)&att_mask[(size_t)qr1 * SEQ + col];
            s[nt][0] = (s[nt][0] + rrow0[id0.x]) * 0.125f - 10000.f * (1.f - (float)mk0.x);
            s[nt][1] = (s[nt][1] + rrow0[id0.y]) * 0.125f - 10000.f * (1.f - (float)mk0.y);
            s[nt][2] = (s[nt][2] + rrow1[id1.x]) * 0.125f - 10000.f * (1.f - (float)mk1.x);
            s[nt][3] = (s[nt][3] + rrow1[id1.y]) * 0.125f - 10000.f * (1.f - (float)mk1.y);
        }

        // ---- online softmax ----
        float tm0 = -1e30f, tm1 = -1e30f;
        #pragma unroll
        for (int nt = 0; nt < 8; nt++) {
            tm0 = fmaxf(tm0, fmaxf(s[nt][0], s[nt][1]));
            tm1 = fmaxf(tm1, fmaxf(s[nt][2], s[nt][3]));
        }
        tm0 = fmaxf(tm0, __shfl_xor_sync(0xffffffffu, tm0, 1, 4));
        tm0 = fmaxf(tm0, __shfl_xor_sync(0xffffffffu, tm0, 2, 4));
        tm1 = fmaxf(tm1, __shfl_xor_sync(0xffffffffu, tm1, 1, 4));
        tm1 = fmaxf(tm1, __shfl_xor_sync(0xffffffffu, tm1, 2, 4));
        float nm0 = fmaxf(m0, tm0), nm1 = fmaxf(m1, tm1);
        float c0 = __expf(m0 - nm0), c1 = __expf(m1 - nm1);
        m0 = nm0; m1 = nm1;
        float rs0 = 0.f, rs1 = 0.f;
        #pragma unroll
        for (int nt = 0; nt < 8; nt++) {
            s[nt][0] = __expf(s[nt][0] - nm0);
            s[nt][1] = __expf(s[nt][1] - nm0);
            s[nt][2] = __expf(s[nt][2] - nm1);
            s[nt][3] = __expf(s[nt][3] - nm1);
            rs0 += s[nt][0] + s[nt][1];
            rs1 += s[nt][2] + s[nt][3];
        }
        rs0 += __shfl_xor_sync(0xffffffffu, rs0, 1, 4);
        rs0 += __shfl_xor_sync(0xffffffffu, rs0, 2, 4);
        rs1 += __shfl_xor_sync(0xffffffffu, rs1, 1, 4);
        rs1 += __shfl_xor_sync(0xffffffffu, rs1, 2, 4);
        l0 = l0 * c0 + rs0;
        l1 = l1 * c1 + rs1;
        #pragma unroll
        for (int nt = 0; nt < 8; nt++) {
            oacc[nt][0] *= c0; oacc[nt][1] *= c0;
            oacc[nt][2] *= c1; oacc[nt][3] *= c1;
        }

        // ---- stage P (tf32) into QPs — warp-private rows ----
        #pragma unroll
        for (int nt = 0; nt < 8; nt++) {
            int col = nt * 8 + 2 * t;
            *(float2*)&QPs[(wq + g)     * SQP + col] =
                make_float2(tf32r(s[nt][0]), tf32r(s[nt][1]));
            *(float2*)&QPs[(wq + g + 8) * SQP + col] =
                make_float2(tf32r(s[nt][2]), tf32r(s[nt][3]));
        }
        __syncwarp();

        // ---- O += P @ V ----
        #pragma unroll
        for (int ks = 0; ks < 8; ks++) {
            float pa[4];
            pa[0] = QPs[(wq + g)     * SQP + ks * 8 + t];
            pa[1] = QPs[(wq + g + 8) * SQP + ks * 8 + t];
            pa[2] = QPs[(wq + g)     * SQP + ks * 8 + t + 4];
            pa[3] = QPs[(wq + g + 8) * SQP + ks * 8 + t + 4];
            #pragma unroll
            for (int nt = 0; nt < 8; nt++) {
                float b[2];
                b[0] = Vs[(ks * 8 + t)     * SVV + nt * 8 + g];
                b[1] = Vs[(ks * 8 + t + 4) * SVV + nt * 8 + g];
                mma_tf32(oacc[nt], pa, b);
            }
        }

        __syncthreads();    // everyone done reading Vs -> safe to refill

        if (tile + 1 < SEQ / 64) {      // prefetch V(tile+1)
            #pragma unroll
            for (int j = 0; j < 8; j++) {
                int idx = tid + 128 * j;
                int row = idx >> 4, c4 = (idx & 15) * 4;
                CPA16(vsu + (row * SVV + c4) * 4,
                      &g_V[(size_t)(k0 + 64 + row) * HID + h * DHEAD + c4]);
            }
            CPCOMMIT();
        }
    }

    // ---- normalize + write ctx (fp32) ----
    float inv0 = 1.f / l0, inv1 = 1.f / l1;
    #pragma unroll
    for (int nt = 0; nt < 8; nt++) {
        int d = h * DHEAD + nt * 8 + 2 * t;
        *(float2*)&g_ctx[(size_t)qr0 * HID + d] =
            make_float2(oacc[nt][0] * inv0, oacc[nt][1] * inv0);
        *(float2*)&g_ctx[(size_t)qr1 * HID + d] =
            make_float2(oacc[nt][2] * inv1, oacc[nt][3] * inv1);
    }
}

// ---------------------------------------------------------------------------
// launch
// ---------------------------------------------------------------------------
extern "C" void kernel_launch(void* const* d_in, const int* in_sizes, int n_in,
                              void* d_out, int out_size)
{
    (void)in_sizes; (void)n_in; (void)out_size;
    const float* x        = (const float*)d_in[0];
    const int*   att_mask = (const int*)  d_in[1];
    const int*   rel_ids  = (const int*)  d_in[2];
    const float* Wq       = (const float*)d_in[3];
    const float* bq       = (const float*)d_in[4];
    const float* Wk       = (const float*)d_in[5];
    const float* bk       = (const float*)d_in[6];
    const float* Wv       = (const float*)d_in[7];
    const float* bv       = (const float*)d_in[8];
    const float* rel_emb  = (const float*)d_in[9];
    const float* rel_bias = (const float*)d_in[10];
    const float* Wo       = (const float*)d_in[11];
    const float* bo       = (const float*)d_in[12];
    float* out = (float*)d_out;

    float *pQ, *pK, *pV, *pCtx;
    cudaGetSymbolAddress((void**)&pQ,   g_Q);
    cudaGetSymbolAddress((void**)&pK,   g_K);
    cudaGetSymbolAddress((void**)&pV,   g_V);
    cudaGetSymbolAddress((void**)&pCtx, g_ctx);

    cudaFuncSetAttribute(attn_kernel,
                         cudaFuncAttributeMaxDynamicSharedMemorySize,
                         ATTN_SMEM_BYTES);

    dim3 ggrid(HID / 64, SEQ / 128);    // 16 x 16 = 256 blocks
    gemm_tf32<1><<<ggrid, 256>>>(x, Wq, bq, pQ, SEQ, HID, HID);
    gemm_tf32<1><<<ggrid, 256>>>(x, Wk, bk, pK, SEQ, HID, HID);
    gemm_tf32<1><<<ggrid, 256>>>(x, Wv, bv, pV, SEQ, HID, HID);

    attn_kernel<<<dim3(SEQ / 64, NHEAD), 128, ATTN_SMEM_BYTES>>>(
        att_mask, rel_ids, rel_emb, rel_bias);

    gemm_tf32<0><<<ggrid, 256>>>(pCtx, Wo, bo, out, SEQ, HID, HID);
}

// round 11
// speedup vs baseline: 1.1653x; 1.1653x over previous
#include <cuda_runtime.h>
#include <math.h>
#include <stdint.h>

#define HID 1024
#define NHEAD 16
#define DHEAD 64
#define RVOC 32
#define SEQ 2048

// ---------------------------------------------------------------------------
// Scratch (no allocations allowed -> __device__ globals)
// ---------------------------------------------------------------------------
__device__ float g_Q[SEQ * HID];    // tf32-rounded by gemm epilogue
__device__ float g_K[SEQ * HID];    // tf32-rounded
__device__ float g_V[SEQ * HID];    // tf32-rounded
__device__ float g_ctx[SEQ * HID];  // fp32

// ---------------------------------------------------------------------------
// helpers
// ---------------------------------------------------------------------------
__device__ __forceinline__ float tf32r(float x) {
    asm("cvt.rna.tf32.f32 %0, %0;" : "+f"(x));
    return x;
}
__device__ __forceinline__ float4 tf32r4(float4 v) {
    v.x = tf32r(v.x); v.y = tf32r(v.y); v.z = tf32r(v.z); v.w = tf32r(v.w);
    return v;
}
__device__ __forceinline__ void mma_tf32(float* c, const float* a, const float* b) {
    const uint32_t* A = reinterpret_cast<const uint32_t*>(a);
    const uint32_t* B = reinterpret_cast<const uint32_t*>(b);
    asm volatile(
        "mma.sync.aligned.m16n8k8.row.col.f32.tf32.tf32.f32 "
        "{%0,%1,%2,%3}, {%4,%5,%6,%7}, {%8,%9}, {%0,%1,%2,%3};\n"
        : "+f"(c[0]), "+f"(c[1]), "+f"(c[2]), "+f"(c[3])
        : "r"(A[0]), "r"(A[1]), "r"(A[2]), "r"(A[3]), "r"(B[0]), "r"(B[1]));
}
__device__ __forceinline__ uint32_t s2u(const void* p) {
    return (uint32_t)__cvta_generic_to_shared(p);
}
#define CPA16(dst, src) \
    asm volatile("cp.async.ca.shared.global [%0], [%1], 16;\n" :: "r"(dst), "l"(src))
#define CPCOMMIT() asm volatile("cp.async.commit_group;\n")
#define CPWAIT(n)  asm volatile("cp.async.wait_group %0;\n" :: "n"(n))

// softmax in log2 space: exp(x) = exp2(x * log2e)
#define LOG2E     1.4426950408889634f
#define SM_SCALE  (0.125f * LOG2E)      // (1/sqrt(64)) * log2e
#define MASK_C    (10000.0f * LOG2E)

// ---------------------------------------------------------------------------
// tf32 tensor-core GEMM core (R5 config): C[M,N] = A[M,K] @ B[K,N] + bias[N]
// 128x128 block tile, BK=16, 256 threads = 8 warps (4m x 2n), warp 32x64.
// ---------------------------------------------------------------------------
#define SA 20     // As row stride (floats)
#define SB 136    // Bs row stride (floats)

template<int ROUND>
__device__ __forceinline__ void gemm_body(
    const float* __restrict__ A, const float* __restrict__ B,
    const float* __restrict__ bias, float* __restrict__ C,
    int M, int N, int K, int bx, int by)
{
    __shared__ float As[128 * SA];
    __shared__ float Bs[16 * SB];

    const int tid  = threadIdx.x;
    const int lane = tid & 31;
    const int wid  = tid >> 5;
    const int g    = lane >> 2;
    const int t    = lane & 3;
    const int wm   = (wid & 3) * 32;
    const int wn   = (wid >> 2) * 64;
    const int brow = by * 128;
    const int bcol = bx * 128;

    const int arow = tid >> 1;
    const int akc  = (tid & 1) * 8;
    const int br   = tid >> 5;
    const int bnc  = (tid & 31) * 4;

    float acc[2][8][4];
    #pragma unroll
    for (int mt = 0; mt < 2; mt++)
        #pragma unroll
        for (int nt = 0; nt < 8; nt++)
            #pragma unroll
            for (int i = 0; i < 4; i++) acc[mt][nt][i] = 0.f;

    float4 pa0 = *(const float4*)&A[(size_t)(brow + arow) * K + akc];
    float4 pa1 = *(const float4*)&A[(size_t)(brow + arow) * K + akc + 4];
    float4 pb0 = *(const float4*)&B[(size_t)br * N + bcol + bnc];
    float4 pb1 = *(const float4*)&B[(size_t)(br + 8) * N + bcol + bnc];

    for (int k0 = 0; k0 < K; k0 += 16) {
        *(float4*)&As[arow * SA + akc]     = tf32r4(pa0);
        *(float4*)&As[arow * SA + akc + 4] = tf32r4(pa1);
        *(float4*)&Bs[br * SB + bnc]       = tf32r4(pb0);
        *(float4*)&Bs[(br + 8) * SB + bnc] = tf32r4(pb1);
        __syncthreads();

        int k1 = k0 + 16;
        if (k1 < K) {
            pa0 = *(const float4*)&A[(size_t)(brow + arow) * K + k1 + akc];
            pa1 = *(const float4*)&A[(size_t)(brow + arow) * K + k1 + akc + 4];
            pb0 = *(const float4*)&B[(size_t)(k1 + br) * N + bcol + bnc];
            pb1 = *(const float4*)&B[(size_t)(k1 + br + 8) * N + bcol + bnc];
        }

        #pragma unroll
        for (int ks = 0; ks < 16; ks += 8) {
            float a[2][4], b[8][2];
            #pragma unroll
            for (int mt = 0; mt < 2; mt++) {
                a[mt][0] = As[(wm + mt * 16 + g)     * SA + ks + t];
                a[mt][1] = As[(wm + mt * 16 + g + 8) * SA + ks + t];
                a[mt][2] = As[(wm + mt * 16 + g)     * SA + ks + t + 4];
                a[mt][3] = As[(wm + mt * 16 + g + 8) * SA + ks + t + 4];
            }
            #pragma unroll
            for (int nt = 0; nt < 8; nt++) {
                b[nt][0] = Bs[(ks + t)     * SB + wn + nt * 8 + g];
                b[nt][1] = Bs[(ks + t + 4) * SB + wn + nt * 8 + g];
            }
            #pragma unroll
            for (int mt = 0; mt < 2; mt++)
                #pragma unroll
                for (int nt = 0; nt < 8; nt++)
                    mma_tf32(acc[mt][nt], a[mt], b[nt]);
        }
        __syncthreads();
    }

    #pragma unroll
    for (int nt = 0; nt < 8; nt++) {
        const int col = bcol + wn + nt * 8 + 2 * t;
        float2 bv = *(const float2*)&bias[col];
        #pragma unroll
        for (int mt = 0; mt < 2; mt++) {
            int r0 = brow + wm + mt * 16 + g;
            float2 c01 = make_float2(acc[mt][nt][0] + bv.x, acc[mt][nt][1] + bv.y);
            float2 c23 = make_float2(acc[mt][nt][2] + bv.x, acc[mt][nt][3] + bv.y);
            if (ROUND) {
                c01.x = tf32r(c01.x); c01.y = tf32r(c01.y);
                c23.x = tf32r(c23.x); c23.y = tf32r(c23.y);
            }
            *(float2*)&C[(size_t)r0 * N + col]       = c01;
            *(float2*)&C[(size_t)(r0 + 8) * N + col] = c23;
        }
    }
}

// fused QKV: blockIdx.z selects weight/bias/output
__global__ __launch_bounds__(256) void gemm_qkv(
    const float* __restrict__ x,
    const float* __restrict__ Wq, const float* __restrict__ bq,
    const float* __restrict__ Wk, const float* __restrict__ bk,
    const float* __restrict__ Wv, const float* __restrict__ bv,
    float* __restrict__ Q, float* __restrict__ K, float* __restrict__ V)
{
    const int z = blockIdx.z;
    const float* W = (z == 0) ? Wq : (z == 1) ? Wk : Wv;
    const float* b = (z == 0) ? bq : (z == 1) ? bk : bv;
    float*       C = (z == 0) ? Q  : (z == 1) ? K  : V;
    gemm_body<1>(x, W, b, C, SEQ, HID, HID, blockIdx.x, blockIdx.y);
}

__global__ __launch_bounds__(256) void gemm_out(
    const float* __restrict__ A, const float* __restrict__ B,
    const float* __restrict__ bias, float* __restrict__ C)
{
    gemm_body<0>(A, B, bias, C, SEQ, HID, HID, blockIdx.x, blockIdx.y);
}

// ---------------------------------------------------------------------------
// Flash attention, tf32 mma, cp.async K/V pipeline (R6 structure, exp2 softmax)
// Block = (64 q rows, 1 head), 128 thr, 4 warps; warp = 16q x 64keys.
// smem (floats), 64KB -> 3 blocks/SM:
//   QPs[64][76] | Ks[64][68] | Vs[64][72] | Es[64][40]/Rs[64][32]
// ---------------------------------------------------------------------------
#define SQP 76
#define SKK 68
#define SVV 72
#define SEE 40
#define OFF_K  4864
#define OFF_V  9216
#define OFF_RE 13824
#define ATTN_SMEM_FLOATS 16384
#define ATTN_SMEM_BYTES  (ATTN_SMEM_FLOATS * 4)

__global__ __launch_bounds__(128, 3) void attn_kernel(
    const int* __restrict__ att_mask, const int* __restrict__ rel_ids,
    const float* __restrict__ rel_emb, const float* __restrict__ rel_bias)
{
    extern __shared__ float sm[];
    float* QPs = sm;
    float* Ks  = sm + OFF_K;
    float* Vs  = sm + OFF_V;
    float* Es  = sm + OFF_RE;
    float* Rs  = sm + OFF_RE;

    const int h    = blockIdx.y;
    const int q0   = blockIdx.x * 64;
    const int tid  = threadIdx.x;
    const int lane = tid & 31;
    const int wid  = tid >> 5;
    const int g    = lane >> 2;
    const int t    = lane & 3;
    const int wq   = wid * 16;

    const uint32_t ksu = s2u(Ks);
    const uint32_t vsu = s2u(Vs);

    // ---- cp.async K(0), V(0) (overlaps prologue) ----
    #pragma unroll
    for (int j = 0; j < 8; j++) {
        int idx = tid + 128 * j;
        int row = idx >> 4, c4 = (idx & 15) * 4;
        CPA16(ksu + (row * SKK + c4) * 4,
              &g_K[(size_t)row * HID + h * DHEAD + c4]);
    }
    CPCOMMIT();
    #pragma unroll
    for (int j = 0; j < 8; j++) {
        int idx = tid + 128 * j;
        int row = idx >> 4, c4 = (idx & 15) * 4;
        CPA16(vsu + (row * SVV + c4) * 4,
              &g_V[(size_t)row * HID + h * DHEAD + c4]);
    }
    CPCOMMIT();

    // ---- stage Q (already tf32) and rel_emb^T ----
    #pragma unroll
    for (int i = tid; i < 64 * 16; i += 128) {
        int row = i >> 4, dc = (i & 15) * 4;
        *(float4*)&QPs[row * SQP + dc] =
            *(const float4*)&g_Q[(size_t)(q0 + row) * HID + h * DHEAD + dc];
    }
    #pragma unroll
    for (int i = tid; i < 32 * 16; i += 128) {
        int r = i >> 4, dc = (i & 15) * 4;
        float4 v = *(const float4*)&rel_emb[((size_t)r * NHEAD + h) * DHEAD + dc];
        Es[(dc + 0) * SEE + r] = tf32r(v.x);
        Es[(dc + 1) * SEE + r] = tf32r(v.y);
        Es[(dc + 2) * SEE + r] = tf32r(v.z);
        Es[(dc + 3) * SEE + r] = tf32r(v.w);
    }
    __syncthreads();

    // ---- hoist Q A-fragments ----
    float qa[8][4];
    #pragma unroll
    for (int ks = 0; ks < 8; ks++) {
        qa[ks][0] = QPs[(wq + g)     * SQP + ks * 8 + t];
        qa[ks][1] = QPs[(wq + g + 8) * SQP + ks * 8 + t];
        qa[ks][2] = QPs[(wq + g)     * SQP + ks * 8 + t + 4];
        qa[ks][3] = QPs[(wq + g + 8) * SQP + ks * 8 + t + 4];
    }

    // ---- rel scores ----
    float rc[4][4];
    #pragma unroll
    for (int nt = 0; nt < 4; nt++)
        #pragma unroll
        for (int i = 0; i < 4; i++) rc[nt][i] = 0.f;
    #pragma unroll
    for (int ks = 0; ks < 8; ks++)
        #pragma unroll
        for (int nt = 0; nt < 4; nt++) {
            float b[2];
            b[0] = Es[(ks * 8 + t)     * SEE + nt * 8 + g];
            b[1] = Es[(ks * 8 + t + 4) * SEE + nt * 8 + g];
            mma_tf32(rc[nt], qa[ks], b);
        }
    __syncthreads();
    #pragma unroll
    for (int nt = 0; nt < 4; nt++) {
        int r = nt * 8 + 2 * t;
        float bx = rel_bias[(size_t)r * NHEAD + h];
        float by = rel_bias[(size_t)(r + 1) * NHEAD + h];
        Rs[(wq + g)     * 32 + r]     = rc[nt][0] + bx;
        Rs[(wq + g)     * 32 + r + 1] = rc[nt][1] + by;
        Rs[(wq + g + 8) * 32 + r]     = rc[nt][2] + bx;
        Rs[(wq + g + 8) * 32 + r + 1] = rc[nt][3] + by;
    }
    __syncwarp();

    float oacc[8][4];
    #pragma unroll
    for (int nt = 0; nt < 8; nt++)
        #pragma unroll
        for (int i = 0; i < 4; i++) oacc[nt][i] = 0.f;
    float m0 = -1e30f, m1 = -1e30f, l0 = 0.f, l1 = 0.f;

    const int qr0 = q0 + wq + g;
    const int qr1 = qr0 + 8;
    const float* rrow0 = &Rs[(wq + g) * 32];
    const float* rrow1 = &Rs[(wq + g + 8) * 32];

    for (int tile = 0; tile < SEQ / 64; tile++) {
        const int k0 = tile * 64;

        CPWAIT(1);
        __syncthreads();

        // ---- S = Q @ K^T ----
        float s[8][4];
        #pragma unroll
        for (int nt = 0; nt < 8; nt++)
            #pragma unroll
            for (int i = 0; i < 4; i++) s[nt][i] = 0.f;
        #pragma unroll
        for (int ks = 0; ks < 8; ks++)
            #pragma unroll
            for (int nt = 0; nt < 8; nt++) {
                float b[2];
                b[0] = Ks[(nt * 8 + g) * SKK + ks * 8 + t];
                b[1] = Ks[(nt * 8 + g) * SKK + ks * 8 + t + 4];
                mma_tf32(s[nt], qa[ks], b);
            }

        CPWAIT(0);
        __syncthreads();

        if (tile + 1 < SEQ / 64) {
            #pragma unroll
            for (int j = 0; j < 8; j++) {
                int idx = tid + 128 * j;
                int row = idx >> 4, c4 = (idx & 15) * 4;
                CPA16(ksu + (row * SKK + c4) * 4,
                      &g_K[(size_t)(k0 + 64 + row) * HID + h * DHEAD + c4]);
            }
            CPCOMMIT();
        }

        // ---- rel gather + scale(log2e) + mask: s' in log2 units ----
        #pragma unroll
        for (int nt = 0; nt < 8; nt++) {
            const int col = k0 + nt * 8 + 2 * t;
            int2 id0 = *(const int2*)&rel_ids[(size_t)qr0 * SEQ + col];
            int2 id1 = *(const int2*)&rel_ids[(size_t)qr1 * SEQ + col];
            int2 mk0 = *(const int2*)&att_mask[(size_t)qr0 * SEQ + col];
            int2 mk1 = *(const int2*)&att_mask[(size_t)qr1 * SEQ + col];
            // mterm = -MASK_C * (1 - mask)
            float mt00 = fmaf((float)mk0.x, MASK_C, -MASK_C);
            float mt01 = fmaf((float)mk0.y, MASK_C, -MASK_C);
            float mt10 = fmaf((float)mk1.x, MASK_C, -MASK_C);
            float mt11 = fmaf((float)mk1.y, MASK_C, -MASK_C);
            s[nt][0] = fmaf(s[nt][0] + rrow0[id0.x], SM_SCALE, mt00);
            s[nt][1] = fmaf(s[nt][1] + rrow0[id0.y], SM_SCALE, mt01);
            s[nt][2] = fmaf(s[nt][2] + rrow1[id1.x], SM_SCALE, mt10);
            s[nt][3] = fmaf(s[nt][3] + rrow1[id1.y], SM_SCALE, mt11);
        }

        // ---- online softmax in exp2 space ----
        float tm0 = -1e30f, tm1 = -1e30f;
        #pragma unroll
        for (int nt = 0; nt < 8; nt++) {
            tm0 = fmaxf(tm0, fmaxf(s[nt][0], s[nt][1]));
            tm1 = fmaxf(tm1, fmaxf(s[nt][2], s[nt][3]));
        }
        tm0 = fmaxf(tm0, __shfl_xor_sync(0xffffffffu, tm0, 1, 4));
        tm0 = fmaxf(tm0, __shfl_xor_sync(0xffffffffu, tm0, 2, 4));
        tm1 = fmaxf(tm1, __shfl_xor_sync(0xffffffffu, tm1, 1, 4));
        tm1 = fmaxf(tm1, __shfl_xor_sync(0xffffffffu, tm1, 2, 4));
        float nm0 = fmaxf(m0, tm0), nm1 = fmaxf(m1, tm1);
        float c0 = exp2f(m0 - nm0), c1 = exp2f(m1 - nm1);
        m0 = nm0; m1 = nm1;
        float rs0 = 0.f, rs1 = 0.f;
        #pragma unroll
        for (int nt = 0; nt < 8; nt++) {
            s[nt][0] = exp2f(s[nt][0] - nm0);
            s[nt][1] = exp2f(s[nt][1] - nm0);
            s[nt][2] = exp2f(s[nt][2] - nm1);
            s[nt][3] = exp2f(s[nt][3] - nm1);
            rs0 += s[nt][0] + s[nt][1];
            rs1 += s[nt][2] + s[nt][3];
        }
        rs0 += __shfl_xor_sync(0xffffffffu, rs0, 1, 4);
        rs0 += __shfl_xor_sync(0xffffffffu, rs0, 2, 4);
        rs1 += __shfl_xor_sync(0xffffffffu, rs1, 1, 4);
        rs1 += __shfl_xor_sync(0xffffffffu, rs1, 2, 4);
        l0 = l0 * c0 + rs0;
        l1 = l1 * c1 + rs1;
        #pragma unroll
        for (int nt = 0; nt < 8; nt++) {
            oacc[nt][0] *= c0; oacc[nt][1] *= c0;
            oacc[nt][2] *= c1; oacc[nt][3] *= c1;
        }

        // ---- stage P (tf32) — warp-private rows ----
        #pragma unroll
        for (int nt = 0; nt < 8; nt++) {
            int col = nt * 8 + 2 * t;
            *(float2*)&QPs[(wq + g)     * SQP + col] =
                make_float2(tf32r(s[nt][0]), tf32r(s[nt][1]));
            *(float2*)&QPs[(wq + g + 8) * SQP + col] =
                make_float2(tf32r(s[nt][2]), tf32r(s[nt][3]));
        }
        __syncwarp();

        // ---- O += P @ V ----
        #pragma unroll
        for (int ks = 0; ks < 8; ks++) {
            float pa[4];
            pa[0] = QPs[(wq + g)     * SQP + ks * 8 + t];
            pa[1] = QPs[(wq + g + 8) * SQP + ks * 8 + t];
            pa[2] = QPs[(wq + g)     * SQP + ks * 8 + t + 4];
            pa[3] = QPs[(wq + g + 8) * SQP + ks * 8 + t + 4];
            #pragma unroll
            for (int nt = 0; nt < 8; nt++) {
                float b[2];
                b[0] = Vs[(ks * 8 + t)     * SVV + nt * 8 + g];
                b[1] = Vs[(ks * 8 + t + 4) * SVV + nt * 8 + g];
                mma_tf32(oacc[nt], pa, b);
            }
        }

        __syncthreads();

        if (tile + 1 < SEQ / 64) {
            #pragma unroll
            for (int j = 0; j < 8; j++) {
                int idx = tid + 128 * j;
                int row = idx >> 4, c4 = (idx & 15) * 4;
                CPA16(vsu + (row * SVV + c4) * 4,
                      &g_V[(size_t)(k0 + 64 + row) * HID + h * DHEAD + c4]);
            }
            CPCOMMIT();
        }
    }

    // ---- normalize + write ctx ----
    float inv0 = 1.f / l0, inv1 = 1.f / l1;
    #pragma unroll
    for (int nt = 0; nt < 8; nt++) {
        int d = h * DHEAD + nt * 8 + 2 * t;
        *(float2*)&g_ctx[(size_t)qr0 * HID + d] =
            make_float2(oacc[nt][0] * inv0, oacc[nt][1] * inv0);
        *(float2*)&g_ctx[(size_t)qr1 * HID + d] =
            make_float2(oacc[nt][2] * inv1, oacc[nt][3] * inv1);
    }
}

// ---------------------------------------------------------------------------
// launch
// ---------------------------------------------------------------------------
extern "C" void kernel_launch(void* const* d_in, const int* in_sizes, int n_in,
                              void* d_out, int out_size)
{
    (void)in_sizes; (void)n_in; (void)out_size;
    const float* x        = (const float*)d_in[0];
    const int*   att_mask = (const int*)  d_in[1];
    const int*   rel_ids  = (const int*)  d_in[2];
    const float* Wq       = (const float*)d_in[3];
    const float* bq       = (const float*)d_in[4];
    const float* Wk       = (const float*)d_in[5];
    const float* bk       = (const float*)d_in[6];
    const float* Wv       = (const float*)d_in[7];
    const float* bv       = (const float*)d_in[8];
    const float* rel_emb  = (const float*)d_in[9];
    const float* rel_bias = (const float*)d_in[10];
    const float* Wo       = (const float*)d_in[11];
    const float* bo       = (const float*)d_in[12];
    float* out = (float*)d_out;

    float *pQ, *pK, *pV, *pCtx;
    cudaGetSymbolAddress((void**)&pQ,   g_Q);
    cudaGetSymbolAddress((void**)&pK,   g_K);
    cudaGetSymbolAddress((void**)&pV,   g_V);
    cudaGetSymbolAddress((void**)&pCtx, g_ctx);

    cudaFuncSetAttribute(attn_kernel,
                         cudaFuncAttributeMaxDynamicSharedMemorySize,
                         ATTN_SMEM_BYTES);

    dim3 qkvgrid(HID / 128, SEQ / 128, 3);   // 8 x 16 x 3 = 384 blocks
    gemm_qkv<<<qkvgrid, 256>>>(x, Wq, bq, Wk, bk, Wv, bv, pQ, pK, pV);

    attn_kernel<<<dim3(SEQ / 64, NHEAD), 128, ATTN_SMEM_BYTES>>>(
        att_mask, rel_ids, rel_emb, rel_bias);

    dim3 ogrid(HID / 128, SEQ / 128);        // 8 x 16 = 128 blocks
    gemm_out<<<ogrid, 256>>>(pCtx, Wo, bo, out);
}